// round 1
// baseline (speedup 1.0000x reference)
#include <cuda_runtime.h>
#include <cstdint>

// ---------------- problem constants ----------------
constexpr int NN   = 1048576;   // nodes
constexpr int EE   = 4194304;   // edges
constexpr int BB   = 2048;      // batch / graphs
constexpr int SEQL = 1000;      // protein sequence length
constexpr float BN_EPS = 1e-5f;

// ---------------- device scratch (static, no allocs) ----------------
__device__ float  g_z  [(size_t)NN*32];   // projected features / y (in-place)
__device__ float  g_agg[(size_t)NN*32];   // neighbor aggregation
__device__ float  g_h  [(size_t)NN*32];   // post-BN features
__device__ double g_stats[64];            // per-channel sum / sumsq
__device__ float  g_pooled[BB*32];
__device__ float  g_cnt[BB];
__device__ float  g_xj[BB*256];           // concat [xdv | xtv]
__device__ float  g_A [(size_t)BB*6656];  // histogram-weighted conv weights
__device__ float  g_T [6656*128];         // folded emb x fct_w
__device__ float  g_tb[128];              // folded bias
__device__ float  g_z1[BB*1024];
__device__ float  g_z2[BB*256];
__device__ int    g_is64;

// ---------------- helpers ----------------
__device__ __forceinline__ long long idx_at(const void* p, long long i, int is64) {
    if (is64) return ((const long long*)p)[i];
    return (long long)((const int*)p)[i];
}

// Detect whether index tensors are int64 (upper words all zero) or int32.
__global__ void k_detect(const int* ei) {
    int nz = 0;
    for (int i = 0; i < 256; i++) nz += (ei[2*i + 1] != 0);
    g_is64 = (nz == 0) ? 1 : 0;
}

// ---------------- GIN: projection  z = x @ Wa  (no bias) ----------------
template<int K>
__global__ void k_project(const float* __restrict__ x, const float* __restrict__ wa) {
    __shared__ float ws[K*32];
    for (int i = threadIdx.x; i < K*32; i += 128) ws[i] = wa[i];
    __syncthreads();
    int n = blockIdx.x * 128 + threadIdx.x;
    const float* xr = x + (size_t)n * K;
    float u[32];
#pragma unroll
    for (int j = 0; j < 32; j++) u[j] = 0.f;
#pragma unroll 4
    for (int k = 0; k < K; k++) {
        float tv = xr[k];
#pragma unroll
        for (int j4 = 0; j4 < 8; j4++) {
            float4 w4 = *(const float4*)&ws[k*32 + j4*4];
            u[j4*4+0] += tv * w4.x;
            u[j4*4+1] += tv * w4.y;
            u[j4*4+2] += tv * w4.z;
            u[j4*4+3] += tv * w4.w;
        }
    }
    float4* zo = (float4*)(g_z + (size_t)n * 32);
#pragma unroll
    for (int i = 0; i < 8; i++)
        zo[i] = make_float4(u[i*4], u[i*4+1], u[i*4+2], u[i*4+3]);
}

// ---------------- GIN: scatter  agg[dst] += z[src]  (32-dim, float4 atomics) ----------------
__global__ void k_scatter(const void* __restrict__ ei) {
    int e = blockIdx.x * 256 + threadIdx.x;
    int is64 = g_is64;
    long long s = idx_at(ei, e, is64);
    long long d = idx_at(ei, (long long)EE + e, is64);
    const float4* zs = (const float4*)(g_z + s * 32);
    float4*       ad = (float4*)(g_agg + d * 32);
#pragma unroll
    for (int i = 0; i < 8; i++) {
        float4 v = zs[i];
        atomicAdd(&ad[i], v);
    }
}

// ---------------- GIN: finish  y = relu(relu(z+agg+ba) @ Wb + bb), stats in double ----------------
__global__ void k_finish(const float* __restrict__ ba, const float* __restrict__ wb,
                         const float* __restrict__ bb) {
    __shared__ float  ws[1024];
    __shared__ float  bas[32], bbs[32];
    __shared__ float  ys[128*33];
    __shared__ double blk[64];
    int tid = threadIdx.x;
    for (int i = tid; i < 1024; i += 128) ws[i] = wb[i];
    if (tid < 32) { bas[tid] = ba[tid]; bbs[tid] = bb[tid]; }
    if (tid < 64) blk[tid] = 0.0;
    __syncthreads();
    int n = blockIdx.x * 128 + tid;
    float4*       zp = (float4*)(g_z + (size_t)n * 32);
    const float4* ap = (const float4*)(g_agg + (size_t)n * 32);
    float u[32];
#pragma unroll
    for (int i = 0; i < 8; i++) {
        float4 a = zp[i], b = ap[i];
        u[i*4+0] = fmaxf(a.x + b.x + bas[i*4+0], 0.f);
        u[i*4+1] = fmaxf(a.y + b.y + bas[i*4+1], 0.f);
        u[i*4+2] = fmaxf(a.z + b.z + bas[i*4+2], 0.f);
        u[i*4+3] = fmaxf(a.w + b.w + bas[i*4+3], 0.f);
    }
    float y[32];
#pragma unroll
    for (int j = 0; j < 32; j++) y[j] = 0.f;
#pragma unroll 4
    for (int k = 0; k < 32; k++) {
        float tv = u[k];
#pragma unroll
        for (int j4 = 0; j4 < 8; j4++) {
            float4 w4 = *(const float4*)&ws[k*32 + j4*4];
            y[j4*4+0] += tv * w4.x;
            y[j4*4+1] += tv * w4.y;
            y[j4*4+2] += tv * w4.z;
            y[j4*4+3] += tv * w4.w;
        }
    }
#pragma unroll
    for (int j = 0; j < 32; j++) y[j] = fmaxf(y[j] + bbs[j], 0.f);
#pragma unroll
    for (int i = 0; i < 8; i++)
        zp[i] = make_float4(y[i*4], y[i*4+1], y[i*4+2], y[i*4+3]);
#pragma unroll
    for (int j = 0; j < 32; j++) ys[tid*33 + j] = y[j];
    __syncthreads();
    // transpose-style reduce: thread (q,c) sums channel c over 32 nodes
    int c = tid & 31, q = tid >> 5;
    float s1 = 0.f, s2 = 0.f;
#pragma unroll 4
    for (int i = 0; i < 32; i++) {
        float v = ys[(q*32 + i)*33 + c];
        s1 += v; s2 += v * v;
    }
    atomicAdd(&blk[c],      (double)s1);
    atomicAdd(&blk[32 + c], (double)s2);
    __syncthreads();
    if (tid < 64) atomicAdd(&g_stats[tid], blk[tid]);
}

// ---------------- GIN: batch-norm apply (training-mode batch stats) ----------------
__global__ void k_bn(const float* __restrict__ g, const float* __restrict__ b) {
    __shared__ float sc[32], sh[32];
    if (threadIdx.x < 32) {
        int c = threadIdx.x;
        double mu  = g_stats[c]      * (1.0 / NN);
        double var = g_stats[32 + c] * (1.0 / NN) - mu * mu;
        float s = g[c] * rsqrtf((float)var + BN_EPS);
        sc[c] = s;
        sh[c] = b[c] - (float)mu * s;
    }
    __syncthreads();
    size_t i = (size_t)blockIdx.x * 256 + threadIdx.x;  // over NN*8 float4s
    int c0 = (int)(i & 7) * 4;
    float4 v = ((const float4*)g_z)[i];
    v.x = v.x * sc[c0+0] + sh[c0+0];
    v.y = v.y * sc[c0+1] + sh[c0+1];
    v.z = v.z * sc[c0+2] + sh[c0+2];
    v.w = v.w * sc[c0+3] + sh[c0+3];
    ((float4*)g_h)[i] = v;
}

// ---------------- global mean pool ----------------
__global__ void k_pool(const void* __restrict__ xb) {
    int n = blockIdx.x * 256 + threadIdx.x;
    long long b = idx_at(xb, n, g_is64);
    atomicAdd(&g_cnt[b], 1.0f);
    const float4* hp = (const float4*)(g_h + (size_t)n * 32);
    float4*       pp = (float4*)(g_pooled + b * 32);
#pragma unroll
    for (int i = 0; i < 8; i++) {
        float4 v = hp[i];
        atomicAdd(&pp[i], v);
    }
}
__global__ void k_div() {
    int i = blockIdx.x * 256 + threadIdx.x;
    g_pooled[i] *= 1.f / fmaxf(g_cnt[i >> 5], 1.f);
}

// ---------------- protein branch: A[b,v,o,k] = sum_c [xt[b,c]==v] * w[o,c,k] ----------------
__global__ void k_abuild(const void* __restrict__ xt, const float* __restrict__ cw) {
    __shared__ float As[26*256];
    int b = blockIdx.x, tid = threadIdx.x;
    for (int i = tid; i < 26*256; i += 256) As[i] = 0.f;
    __syncthreads();
    int is64 = g_is64;
    int o = tid >> 3, k = tid & 7;
    const float* wp = cw + o * (SEQL*8) + k;
    for (int c = 0; c < SEQL; c++) {
        int v = (int)idx_at(xt, (long long)b * SEQL + c, is64);
        As[v*256 + tid] += wp[c*8];
    }
    __syncthreads();
    for (int i = tid; i < 6656; i += 256) g_A[(size_t)b * 6656 + i] = As[i];
}

// ---------------- T[(v,o,k), j] = sum_p emb[v, p+k] * fct_w[(o*121+p)*128 + j] ----------------
__global__ void k_tbuild(const float* __restrict__ emb, const float* __restrict__ fw) {
    __shared__ float es[128];
    int v = blockIdx.x >> 5, o = blockIdx.x & 31;
    int j = threadIdx.x;
    es[j] = emb[v*128 + j];
    __syncthreads();
    float acc[8];
#pragma unroll
    for (int k = 0; k < 8; k++) acc[k] = 0.f;
    for (int p = 0; p < 121; p++) {
        float w = fw[(size_t)(o*121 + p) * 128 + j];
#pragma unroll
        for (int k = 0; k < 8; k++) acc[k] += es[p + k] * w;
    }
#pragma unroll
    for (int k = 0; k < 8; k++)
        g_T[(size_t)(v*256 + o*8 + k) * 128 + j] = acc[k];
}

// tb[j] = fct_b[j] + sum_{o,p} conv_b[o] * fct_w[(o*121+p)*128 + j]
__global__ void k_tbias(const float* __restrict__ fw, const float* __restrict__ fb,
                        const float* __restrict__ cb) {
    int j = threadIdx.x;
    float acc = fb[j];
    for (int o = 0; o < 32; o++) {
        float cbo = cb[o];
        for (int p = 0; p < 121; p++)
            acc += cbo * fw[(size_t)(o*121 + p) * 128 + j];
    }
    g_tb[j] = acc;
}

// ---------------- generic SGEMM: C = [relu](A[MxK] @ W[KxN] + bias), row-major ----------------
// BM=32, BN=64, BK=16, 128 threads, 4x4 register tile. Requires M%32==0, N%64==0, K%16==0.
__global__ void k_sgemm(const float* __restrict__ A, const float* __restrict__ W,
                        const float* __restrict__ bias, float* __restrict__ C,
                        int M, int N, int K, int ldc, int relu) {
    __shared__ float As[16][33];
    __shared__ float Ws[16][65];
    int bm = blockIdx.y * 32, bn = blockIdx.x * 64;
    int tid = threadIdx.x;
    int tm = (tid >> 4) << 2;   // 0..28
    int tn = (tid & 15) << 2;   // 0..60
    float acc[4][4];
#pragma unroll
    for (int i = 0; i < 4; i++)
#pragma unroll
        for (int j = 0; j < 4; j++) acc[i][j] = 0.f;

    for (int k0 = 0; k0 < K; k0 += 16) {
#pragma unroll
        for (int i = 0; i < 4; i++) {          // A tile 32x16
            int f = tid + i * 128;
            int r = f >> 4, c = f & 15;
            As[c][r] = A[(size_t)(bm + r) * K + k0 + c];
        }
#pragma unroll
        for (int i = 0; i < 8; i++) {          // W tile 16x64
            int f = tid + i * 128;
            int r = f >> 6, c = f & 63;
            Ws[r][c] = W[(size_t)(k0 + r) * N + bn + c];
        }
        __syncthreads();
#pragma unroll
        for (int k = 0; k < 16; k++) {
            float a[4], w[4];
#pragma unroll
            for (int i = 0; i < 4; i++) a[i] = As[k][tm + i];
#pragma unroll
            for (int j = 0; j < 4; j++) w[j] = Ws[k][tn + j];
#pragma unroll
            for (int i = 0; i < 4; i++)
#pragma unroll
                for (int j = 0; j < 4; j++) acc[i][j] += a[i] * w[j];
        }
        __syncthreads();
    }
#pragma unroll
    for (int i = 0; i < 4; i++)
#pragma unroll
        for (int j = 0; j < 4; j++) {
            float v = acc[i][j] + bias[bn + tn + j];
            if (relu) v = fmaxf(v, 0.f);
            C[(size_t)(bm + tm + i) * ldc + bn + tn + j] = v;
        }
}

// ---------------- final: out[b] = z2[b] . c3w + c3b ----------------
__global__ void k_final(const float* __restrict__ w, const float* __restrict__ b,
                        float* __restrict__ out) {
    int i = blockIdx.x * 256 + threadIdx.x;
    if (i >= BB) return;
    const float* zr = g_z2 + (size_t)i * 256;
    float acc = 0.f;
#pragma unroll 4
    for (int k = 0; k < 256; k++) acc += zr[k] * w[k];
    out[i] = acc + b[0];
}

// ---------------- host launcher ----------------
extern "C" void kernel_launch(void* const* d_in, const int* in_sizes, int n_in,
                              void* d_out, int out_size) {
    (void)in_sizes; (void)n_in; (void)out_size;
    const float* xd     = (const float*)d_in[0];
    const void*  ei     = d_in[1];
    const void*  xb     = d_in[2];
    const void*  xt     = d_in[3];
    const float* w1a    = (const float*)d_in[4];
    const float* b1a    = (const float*)d_in[5];
    const float* w1b    = (const float*)d_in[6];
    const float* b1b    = (const float*)d_in[7];
    const float* wa     = (const float*)d_in[8];
    const float* ba     = (const float*)d_in[9];
    const float* wb     = (const float*)d_in[10];
    const float* bb     = (const float*)d_in[11];
    const float* bng    = (const float*)d_in[12];
    const float* bnb    = (const float*)d_in[13];
    const float* fcd_w  = (const float*)d_in[14];
    const float* fcd_b  = (const float*)d_in[15];
    const float* emb    = (const float*)d_in[16];
    const float* conv_w = (const float*)d_in[17];
    const float* conv_b = (const float*)d_in[18];
    const float* fct_w  = (const float*)d_in[19];
    const float* fct_b  = (const float*)d_in[20];
    const float* c1w    = (const float*)d_in[21];
    const float* c1b    = (const float*)d_in[22];
    const float* c2w    = (const float*)d_in[23];
    const float* c2b    = (const float*)d_in[24];
    const float* c3w    = (const float*)d_in[25];
    const float* c3b    = (const float*)d_in[26];
    float* out = (float*)d_out;

    void *p_agg, *p_stats, *p_pooled, *p_cnt, *p_xj, *p_A, *p_T, *p_tb, *p_z1, *p_z2;
    cudaGetSymbolAddress(&p_agg,    g_agg);
    cudaGetSymbolAddress(&p_stats,  g_stats);
    cudaGetSymbolAddress(&p_pooled, g_pooled);
    cudaGetSymbolAddress(&p_cnt,    g_cnt);
    cudaGetSymbolAddress(&p_xj,     g_xj);
    cudaGetSymbolAddress(&p_A,      g_A);
    cudaGetSymbolAddress(&p_T,      g_T);
    cudaGetSymbolAddress(&p_tb,     g_tb);
    cudaGetSymbolAddress(&p_z1,     g_z1);
    cudaGetSymbolAddress(&p_z2,     g_z2);

    k_detect<<<1, 1>>>((const int*)ei);

    void* p_h; cudaGetSymbolAddress(&p_h, g_h);
    // ----- 5 GIN layers -----
    for (int L = 0; L < 5; L++) {
        const float* pwa = (L == 0) ? w1a : wa + (L - 1) * 1024;
        const float* pba = (L == 0) ? b1a : ba + (L - 1) * 32;
        const float* pwb = (L == 0) ? w1b : wb + (L - 1) * 1024;
        const float* pbb = (L == 0) ? b1b : bb + (L - 1) * 32;
        if (L == 0) k_project<55><<<NN/128, 128>>>(xd, pwa);
        else        k_project<32><<<NN/128, 128>>>((const float*)p_h, pwa);
        cudaMemsetAsync(p_agg,   0, (size_t)NN * 32 * sizeof(float));
        cudaMemsetAsync(p_stats, 0, 64 * sizeof(double));
        k_scatter<<<EE/256, 256>>>(ei);
        k_finish<<<NN/128, 128>>>(pba, pwb, pbb);
        k_bn<<<(NN*8)/256, 256>>>(bng + L * 32, bnb + L * 32);
    }

    // ----- global mean pool + fc1_xd -----
    cudaMemsetAsync(p_pooled, 0, BB * 32 * sizeof(float));
    cudaMemsetAsync(p_cnt,    0, BB * sizeof(float));
    k_pool<<<NN/256, 256>>>(xb);
    k_div<<<(BB*32)/256, 256>>>();
    k_sgemm<<<dim3(128/64, BB/32), 128>>>((const float*)p_pooled, fcd_w, fcd_b,
                                          (float*)p_xj, BB, 128, 32, 256, 1);

    // ----- protein branch: histogram + folded conv/fc GEMM -----
    k_abuild<<<BB, 256>>>(xt, conv_w);
    k_tbuild<<<26*32, 128>>>(emb, fct_w);
    k_tbias<<<1, 128>>>(fct_w, fct_b, conv_b);
    k_sgemm<<<dim3(128/64, BB/32), 128>>>((const float*)p_A, (const float*)p_T,
                                          (const float*)p_tb, (float*)p_xj + 128,
                                          BB, 128, 6656, 256, 0);

    // ----- classifier -----
    k_sgemm<<<dim3(1024/64, BB/32), 128>>>((const float*)p_xj, c1w, c1b,
                                           (float*)p_z1, BB, 1024, 256, 1024, 1);
    k_sgemm<<<dim3(256/64,  BB/32), 128>>>((const float*)p_z1, c2w, c2b,
                                           (float*)p_z2, BB, 256, 1024, 256, 1);
    k_final<<<(BB + 255)/256, 256>>>(c3w, c3b, out);
}

// round 4
// speedup vs baseline: 1.5551x; 1.5551x over previous
#include <cuda_runtime.h>
#include <cstdint>

// ---------------- problem constants ----------------
constexpr int NN   = 1048576;   // nodes
constexpr int EE   = 4194304;   // edges
constexpr int BB   = 2048;      // batch / graphs
constexpr int SEQL = 1000;      // protein sequence length
constexpr float BN_EPS = 1e-5f;

// ---------------- device scratch (static, no allocs) ----------------
__device__ float  g_z  [(size_t)NN*32];   // ping buffer
__device__ float  g_agg[(size_t)NN*32];   // pong buffer
__device__ double g_stats[64];            // per-channel sum / sumsq (pre-BN y)
__device__ float  g_wfold[1024];          // BN-folded Wa for next layer
__device__ float  g_cfold[32];            // BN-folded constant row
__device__ float  g_pooled[BB*32];
__device__ float  g_xj[BB*256];           // concat [xdv | xtv]
__device__ float  g_A [(size_t)BB*6656];  // histogram-weighted conv weights
__device__ float  g_T [6656*128];         // folded emb x fct_w
__device__ float  g_tb[128];              // folded bias
__device__ float  g_z1[BB*1024];
__device__ float  g_z2[BB*256];
__device__ int    g_is64;
// CSR build
__device__ int    g_deg[NN];
__device__ int    g_off[NN+1];
__device__ int    g_part[4096];
__device__ int    g_cur[NN];
__device__ int    g_csr[EE];

// ---------------- helpers ----------------
__device__ __forceinline__ long long idx_at(const void* p, long long i, int is64) {
    if (is64) return ((const long long*)p)[i];
    return (long long)((const int*)p)[i];
}

__global__ void k_detect(const int* ei) {
    int nz = 0;
    for (int i = 0; i < 256; i++) nz += (ei[2*i + 1] != 0);
    g_is64 = (nz == 0) ? 1 : 0;
}

// ---------------- CSR build ----------------
__global__ void k_deg(const void* __restrict__ ei) {
    int e = blockIdx.x * 256 + threadIdx.x;
    long long d = idx_at(ei, (long long)EE + e, g_is64);
    atomicAdd(&g_deg[(int)d], 1);
}

// block-local exclusive scan of 256 elements
__global__ void k_scan1() {
    __shared__ int s[256];
    int tid = threadIdx.x;
    int i = blockIdx.x * 256 + tid;
    int v = g_deg[i];
    s[tid] = v;
    __syncthreads();
#pragma unroll
    for (int d = 1; d < 256; d <<= 1) {
        int t = (tid >= d) ? s[tid - d] : 0;
        __syncthreads();
        s[tid] += t;
        __syncthreads();
    }
    g_off[i] = s[tid] - v;                  // exclusive within block
    if (tid == 255) g_part[blockIdx.x] = s[255];
}

// scan of 4096 block sums (1 block, 1024 threads, 4 elems/thread)
__global__ void k_scan2() {
    __shared__ int s[1024];
    int t = threadIdx.x;
    int base = t * 4;
    int a0 = g_part[base], a1 = g_part[base+1], a2 = g_part[base+2], a3 = g_part[base+3];
    int sum = a0 + a1 + a2 + a3;
    s[t] = sum;
    __syncthreads();
#pragma unroll
    for (int d = 1; d < 1024; d <<= 1) {
        int tv = (t >= d) ? s[t - d] : 0;
        __syncthreads();
        s[t] += tv;
        __syncthreads();
    }
    int ex = s[t] - sum;
    g_part[base]   = ex;
    g_part[base+1] = ex + a0;
    g_part[base+2] = ex + a0 + a1;
    g_part[base+3] = ex + a0 + a1 + a2;
    if (t == 1023) g_off[NN] = s[1023];
}

__global__ void k_scan3() {
    int i = blockIdx.x * 256 + threadIdx.x;
    int o = g_off[i] + g_part[blockIdx.x];
    g_off[i] = o;
    g_cur[i] = o;
}

__global__ void k_fill(const void* __restrict__ ei) {
    int e = blockIdx.x * 256 + threadIdx.x;
    int is64 = g_is64;
    int s = (int)idx_at(ei, e, is64);
    int d = (int)idx_at(ei, (long long)EE + e, is64);
    int pos = atomicAdd(&g_cur[d], 1);
    g_csr[pos] = s;
}

// ---------------- GIN: projection  z = x @ Wa  (layer 0, raw input) ----------------
template<int K>
__global__ void k_project(const float* __restrict__ x, const float* __restrict__ wa,
                          float* __restrict__ zout) {
    __shared__ float ws[K*32];
    for (int i = threadIdx.x; i < K*32; i += 128) ws[i] = wa[i];
    __syncthreads();
    int n = blockIdx.x * 128 + threadIdx.x;
    const float* xr = x + (size_t)n * K;
    float u[32];
#pragma unroll
    for (int j = 0; j < 32; j++) u[j] = 0.f;
#pragma unroll 4
    for (int k = 0; k < K; k++) {
        float tv = xr[k];
#pragma unroll
        for (int j4 = 0; j4 < 8; j4++) {
            float4 w4 = *(const float4*)&ws[k*32 + j4*4];
            u[j4*4+0] += tv * w4.x;
            u[j4*4+1] += tv * w4.y;
            u[j4*4+2] += tv * w4.z;
            u[j4*4+3] += tv * w4.w;
        }
    }
    float4* zo = (float4*)(zout + (size_t)n * 32);
#pragma unroll
    for (int i = 0; i < 8; i++)
        zo[i] = make_float4(u[i*4], u[i*4+1], u[i*4+2], u[i*4+3]);
}

// ---------------- BN fold: Wa'' = diag(sc) Wa, cvec = sh @ Wa; zero stats ----------------
__global__ void k_fold(const float* __restrict__ wa, const float* __restrict__ g,
                       const float* __restrict__ b) {
    __shared__ float sc[32], sh[32];
    int t = threadIdx.x;
    if (t < 32) {
        double mu  = g_stats[t]      * (1.0 / NN);
        double var = g_stats[32 + t] * (1.0 / NN) - mu * mu;
        float s = g[t] * rsqrtf((float)var + BN_EPS);
        sc[t] = s;
        sh[t] = b[t] - (float)mu * s;
    }
    __syncthreads();
    if (t < 64) g_stats[t] = 0.0;
    int k = t >> 5;
    g_wfold[t] = sc[k] * wa[t];
    if (t < 32) {
        float a = 0.f;
        for (int k2 = 0; k2 < 32; k2++) a += sh[k2] * wa[k2*32 + t];
        g_cfold[t] = a;
    }
}

// ---------------- projection with folded BN: z = y @ Wa'' + cvec (in-place, row-local) ----------------
__global__ void k_projectf(float* __restrict__ buf) {
    __shared__ float ws[1024];
    __shared__ float cs[32];
    int tid = threadIdx.x;
    for (int i = tid; i < 1024; i += 128) ws[i] = g_wfold[i];
    if (tid < 32) cs[tid] = g_cfold[tid];
    __syncthreads();
    int n = blockIdx.x * 128 + tid;
    float4* zr = (float4*)(buf + (size_t)n * 32);
    float x[32];
#pragma unroll
    for (int i = 0; i < 8; i++) {
        float4 v = zr[i];
        x[i*4+0] = v.x; x[i*4+1] = v.y; x[i*4+2] = v.z; x[i*4+3] = v.w;
    }
    float u[32];
#pragma unroll
    for (int j = 0; j < 32; j++) u[j] = cs[j];
#pragma unroll 4
    for (int k = 0; k < 32; k++) {
        float tv = x[k];
#pragma unroll
        for (int j4 = 0; j4 < 8; j4++) {
            float4 w4 = *(const float4*)&ws[k*32 + j4*4];
            u[j4*4+0] += tv * w4.x;
            u[j4*4+1] += tv * w4.y;
            u[j4*4+2] += tv * w4.z;
            u[j4*4+3] += tv * w4.w;
        }
    }
#pragma unroll
    for (int i = 0; i < 8; i++)
        zr[i] = make_float4(u[i*4], u[i*4+1], u[i*4+2], u[i*4+3]);
}

// ---------------- fused gather + GIN finish (zin -> yout, ping-pong safe) ----------------
// y = relu(relu(z_n + sum_{j in N(n)} z_j + ba) @ Wb + bb); stats on y in double
__global__ void k_gfin(const float* __restrict__ zin, float* __restrict__ yout,
                       const float* __restrict__ ba, const float* __restrict__ wb,
                       const float* __restrict__ bb) {
    __shared__ float  ws[1024];
    __shared__ float  bas[32], bbs[32];
    __shared__ float  ys[128*33];
    __shared__ double blk[64];
    int tid = threadIdx.x;
    for (int i = tid; i < 1024; i += 128) ws[i] = wb[i];
    if (tid < 32) { bas[tid] = ba[tid]; bbs[tid] = bb[tid]; }
    if (tid < 64) blk[tid] = 0.0;
    __syncthreads();
    int n = blockIdx.x * 128 + tid;
    const float4* zp = (const float4*)(zin + (size_t)n * 32);
    float u[32];
#pragma unroll
    for (int i = 0; i < 8; i++) {
        float4 a = zp[i];
        u[i*4+0] = a.x; u[i*4+1] = a.y; u[i*4+2] = a.z; u[i*4+3] = a.w;
    }
    // gather neighbor rows (each row = one 128B line)
    int beg = g_off[n], end = g_off[n+1];
    for (int e = beg; e < end; e++) {
        int s = __ldg(&g_csr[e]);
        const float4* r = (const float4*)(zin + (size_t)s * 32);
#pragma unroll
        for (int i = 0; i < 8; i++) {
            float4 v = __ldg(&r[i]);
            u[i*4+0] += v.x; u[i*4+1] += v.y; u[i*4+2] += v.z; u[i*4+3] += v.w;
        }
    }
#pragma unroll
    for (int j = 0; j < 32; j++) u[j] = fmaxf(u[j] + bas[j], 0.f);
    float y[32];
#pragma unroll
    for (int j = 0; j < 32; j++) y[j] = 0.f;
#pragma unroll 4
    for (int k = 0; k < 32; k++) {
        float tv = u[k];
#pragma unroll
        for (int j4 = 0; j4 < 8; j4++) {
            float4 w4 = *(const float4*)&ws[k*32 + j4*4];
            y[j4*4+0] += tv * w4.x;
            y[j4*4+1] += tv * w4.y;
            y[j4*4+2] += tv * w4.z;
            y[j4*4+3] += tv * w4.w;
        }
    }
#pragma unroll
    for (int j = 0; j < 32; j++) y[j] = fmaxf(y[j] + bbs[j], 0.f);
    float4* yo = (float4*)(yout + (size_t)n * 32);
#pragma unroll
    for (int i = 0; i < 8; i++)
        yo[i] = make_float4(y[i*4], y[i*4+1], y[i*4+2], y[i*4+3]);
#pragma unroll
    for (int j = 0; j < 32; j++) ys[tid*33 + j] = y[j];
    __syncthreads();
    int c = tid & 31, q = tid >> 5;
    float s1 = 0.f, s2 = 0.f;
#pragma unroll 4
    for (int i = 0; i < 32; i++) {
        float v = ys[(q*32 + i)*33 + c];
        s1 += v; s2 += v * v;
    }
    atomicAdd(&blk[c],      (double)s1);
    atomicAdd(&blk[32 + c], (double)s2);
    __syncthreads();
    if (tid < 64) atomicAdd(&g_stats[tid], blk[tid]);
}

// ---------------- segment mean-pool over sorted xd_batch + last-layer BN affine ----------------
__device__ __forceinline__ int lbound(const void* xb, int is64, long long target) {
    int lo = 0, hi = NN;
    while (lo < hi) {
        int mid = (lo + hi) >> 1;
        if (idx_at(xb, mid, is64) < target) lo = mid + 1; else hi = mid;
    }
    return lo;
}

__global__ void k_poolseg(const float* __restrict__ ybuf, const void* __restrict__ xb,
                          const float* __restrict__ g, const float* __restrict__ b) {
    __shared__ float red[256];
    __shared__ float sc[32], sh[32];
    __shared__ int bounds[2];
    int tid = threadIdx.x;
    int bidx = blockIdx.x;
    int is64 = g_is64;
    if (tid < 2) bounds[tid] = lbound(xb, is64, (long long)(bidx + tid));
    if (tid >= 32 && tid < 64) {
        int c = tid - 32;
        double mu  = g_stats[c]      * (1.0 / NN);
        double var = g_stats[32 + c] * (1.0 / NN) - mu * mu;
        float s = g[c] * rsqrtf((float)var + BN_EPS);
        sc[c] = s;
        sh[c] = b[c] - (float)mu * s;
    }
    __syncthreads();
    int beg = bounds[0], end = bounds[1];
    int c = tid & 31, q = tid >> 5;
    float s = 0.f;
    for (int n = beg + q; n < end; n += 8) s += ybuf[(size_t)n * 32 + c];
    red[tid] = s;
    __syncthreads();
    for (int o = 128; o >= 32; o >>= 1) {
        if (tid < o) red[tid] += red[tid + o];
        __syncthreads();
    }
    if (tid < 32) {
        int cnt = end - beg;
        float m = (cnt > 0) ? (red[tid] / (float)cnt) * sc[tid] + sh[tid] : 0.f;
        g_pooled[bidx * 32 + tid] = m;
    }
}

// ---------------- protein branch: A[b,v,o,k] = sum_c [xt[b,c]==v] * w[o,c,k] ----------------
__global__ void k_abuild(const void* __restrict__ xt, const float* __restrict__ cw) {
    __shared__ float As[26*256];
    int b = blockIdx.x, tid = threadIdx.x;
    for (int i = tid; i < 26*256; i += 256) As[i] = 0.f;
    __syncthreads();
    int is64 = g_is64;
    int o = tid >> 3, k = tid & 7;
    const float* wp = cw + o * (SEQL*8) + k;
    for (int c = 0; c < SEQL; c++) {
        int v = (int)idx_at(xt, (long long)b * SEQL + c, is64);
        As[v*256 + tid] += wp[c*8];
    }
    __syncthreads();
    for (int i = tid; i < 6656; i += 256) g_A[(size_t)b * 6656 + i] = As[i];
}

// ---------------- T[(v,o,k), j] = sum_p emb[v, p+k] * fct_w[(o*121+p)*128 + j] ----------------
__global__ void k_tbuild(const float* __restrict__ emb, const float* __restrict__ fw) {
    __shared__ float es[128];
    int v = blockIdx.x >> 5, o = blockIdx.x & 31;
    int j = threadIdx.x;
    es[j] = emb[v*128 + j];
    __syncthreads();
    float acc[8];
#pragma unroll
    for (int k = 0; k < 8; k++) acc[k] = 0.f;
    for (int p = 0; p < 121; p++) {
        float w = fw[(size_t)(o*121 + p) * 128 + j];
#pragma unroll
        for (int k = 0; k < 8; k++) acc[k] += es[p + k] * w;
    }
#pragma unroll
    for (int k = 0; k < 8; k++)
        g_T[(size_t)(v*256 + o*8 + k) * 128 + j] = acc[k];
}

__global__ void k_tbias(const float* __restrict__ fw, const float* __restrict__ fb,
                        const float* __restrict__ cb) {
    int j = threadIdx.x;
    float acc = fb[j];
    for (int o = 0; o < 32; o++) {
        float cbo = cb[o];
        for (int p = 0; p < 121; p++)
            acc += cbo * fw[(size_t)(o*121 + p) * 128 + j];
    }
    g_tb[j] = acc;
}

// ---------------- generic SGEMM: C = [relu](A[MxK] @ W[KxN] + bias), row-major ----------------
__global__ void k_sgemm(const float* __restrict__ A, const float* __restrict__ W,
                        const float* __restrict__ bias, float* __restrict__ C,
                        int M, int N, int K, int ldc, int relu) {
    __shared__ float As[16][33];
    __shared__ float Ws[16][65];
    int bm = blockIdx.y * 32, bn = blockIdx.x * 64;
    int tid = threadIdx.x;
    int tm = (tid >> 4) << 2;
    int tn = (tid & 15) << 2;
    float acc[4][4];
#pragma unroll
    for (int i = 0; i < 4; i++)
#pragma unroll
        for (int j = 0; j < 4; j++) acc[i][j] = 0.f;

    for (int k0 = 0; k0 < K; k0 += 16) {
#pragma unroll
        for (int i = 0; i < 4; i++) {
            int f = tid + i * 128;
            int r = f >> 4, c = f & 15;
            As[c][r] = A[(size_t)(bm + r) * K + k0 + c];
        }
#pragma unroll
        for (int i = 0; i < 8; i++) {
            int f = tid + i * 128;
            int r = f >> 6, c = f & 63;
            Ws[r][c] = W[(size_t)(k0 + r) * N + bn + c];
        }
        __syncthreads();
#pragma unroll
        for (int k = 0; k < 16; k++) {
            float a[4], w[4];
#pragma unroll
            for (int i = 0; i < 4; i++) a[i] = As[k][tm + i];
#pragma unroll
            for (int j = 0; j < 4; j++) w[j] = Ws[k][tn + j];
#pragma unroll
            for (int i = 0; i < 4; i++)
#pragma unroll
                for (int j = 0; j < 4; j++) acc[i][j] += a[i] * w[j];
        }
        __syncthreads();
    }
#pragma unroll
    for (int i = 0; i < 4; i++)
#pragma unroll
        for (int j = 0; j < 4; j++) {
            float v = acc[i][j] + bias[bn + tn + j];
            if (relu) v = fmaxf(v, 0.f);
            C[(size_t)(bm + tm + i) * ldc + bn + tn + j] = v;
        }
}

// ---------------- final: out[b] = z2[b] . c3w + c3b ----------------
__global__ void k_final(const float* __restrict__ w, const float* __restrict__ b,
                        float* __restrict__ out) {
    int i = blockIdx.x * 256 + threadIdx.x;
    if (i >= BB) return;
    const float* zr = g_z2 + (size_t)i * 256;
    float acc = 0.f;
#pragma unroll 4
    for (int k = 0; k < 256; k++) acc += zr[k] * w[k];
    out[i] = acc + b[0];
}

// ---------------- host launcher ----------------
extern "C" void kernel_launch(void* const* d_in, const int* in_sizes, int n_in,
                              void* d_out, int out_size) {
    (void)in_sizes; (void)n_in; (void)out_size;
    const float* xd     = (const float*)d_in[0];
    const void*  ei     = d_in[1];
    const void*  xb     = d_in[2];
    const void*  xt     = d_in[3];
    const float* w1a    = (const float*)d_in[4];
    const float* b1a    = (const float*)d_in[5];
    const float* w1b    = (const float*)d_in[6];
    const float* b1b    = (const float*)d_in[7];
    const float* wa     = (const float*)d_in[8];
    const float* ba     = (const float*)d_in[9];
    const float* wb     = (const float*)d_in[10];
    const float* bb     = (const float*)d_in[11];
    const float* bng    = (const float*)d_in[12];
    const float* bnb    = (const float*)d_in[13];
    const float* fcd_w  = (const float*)d_in[14];
    const float* fcd_b  = (const float*)d_in[15];
    const float* emb    = (const float*)d_in[16];
    const float* conv_w = (const float*)d_in[17];
    const float* conv_b = (const float*)d_in[18];
    const float* fct_w  = (const float*)d_in[19];
    const float* fct_b  = (const float*)d_in[20];
    const float* c1w    = (const float*)d_in[21];
    const float* c1b    = (const float*)d_in[22];
    const float* c2w    = (const float*)d_in[23];
    const float* c2b    = (const float*)d_in[24];
    const float* c3w    = (const float*)d_in[25];
    const float* c3b    = (const float*)d_in[26];
    float* out = (float*)d_out;

    void *p_stats, *p_pooled, *p_xj, *p_A, *p_T, *p_tb, *p_z1, *p_deg, *p_z, *p_agg;
    cudaGetSymbolAddress(&p_stats,  g_stats);
    cudaGetSymbolAddress(&p_pooled, g_pooled);
    cudaGetSymbolAddress(&p_xj,     g_xj);
    cudaGetSymbolAddress(&p_A,      g_A);
    cudaGetSymbolAddress(&p_T,      g_T);
    cudaGetSymbolAddress(&p_tb,     g_tb);
    cudaGetSymbolAddress(&p_z1,     g_z1);
    cudaGetSymbolAddress(&p_deg,    g_deg);
    cudaGetSymbolAddress(&p_z,      g_z);
    cudaGetSymbolAddress(&p_agg,    g_agg);
    void* p_z2; cudaGetSymbolAddress(&p_z2, g_z2);

    float* buf[2] = { (float*)p_z, (float*)p_agg };

    k_detect<<<1, 1>>>((const int*)ei);
    cudaMemsetAsync(p_stats, 0, 64 * sizeof(double));

    // ----- CSR build (once, amortized over 5 layers) -----
    cudaMemsetAsync(p_deg, 0, NN * sizeof(int));
    k_deg  <<<EE/256, 256>>>(ei);
    k_scan1<<<4096, 256>>>();
    k_scan2<<<1, 1024>>>();
    k_scan3<<<4096, 256>>>();
    k_fill <<<EE/256, 256>>>(ei);

    // ----- 5 GIN layers (BN folded into next projection; ping-pong buffers) -----
    for (int L = 0; L < 5; L++) {
        float* zin  = buf[L & 1];
        float* yout = buf[(L + 1) & 1];
        if (L == 0) {
            k_project<55><<<NN/128, 128>>>(xd, w1a, zin);
        } else {
            k_fold<<<1, 1024>>>(wa + (L - 1) * 1024, bng + (L - 1) * 32, bnb + (L - 1) * 32);
            k_projectf<<<NN/128, 128>>>(zin);
        }
        const float* pba = (L == 0) ? b1a : ba + (L - 1) * 32;
        const float* pwb = (L == 0) ? w1b : wb + (L - 1) * 1024;
        const float* pbb = (L == 0) ? b1b : bb + (L - 1) * 32;
        k_gfin<<<NN/128, 128>>>(zin, yout, pba, pwb, pbb);
    }

    // ----- segment mean pool (+ layer-5 BN affine) + fc1_xd -----
    // after 5 layers the output lives in buf[5 & 1] = buf[1]
    k_poolseg<<<BB, 256>>>(buf[1], xb, bng + 4 * 32, bnb + 4 * 32);
    k_sgemm<<<dim3(128/64, BB/32), 128>>>((const float*)p_pooled, fcd_w, fcd_b,
                                          (float*)p_xj, BB, 128, 32, 256, 1);

    // ----- protein branch: histogram + folded conv/fc GEMM -----
    k_abuild<<<BB, 256>>>(xt, conv_w);
    k_tbuild<<<26*32, 128>>>(emb, fct_w);
    k_tbias<<<1, 128>>>(fct_w, fct_b, conv_b);
    k_sgemm<<<dim3(128/64, BB/32), 128>>>((const float*)p_A, (const float*)p_T,
                                          (const float*)p_tb, (float*)p_xj + 128,
                                          BB, 128, 6656, 256, 0);

    // ----- classifier -----
    k_sgemm<<<dim3(1024/64, BB/32), 128>>>((const float*)p_xj, c1w, c1b,
                                           (float*)p_z1, BB, 1024, 256, 1024, 1);
    k_sgemm<<<dim3(256/64,  BB/32), 128>>>((const float*)p_z1, c2w, c2b,
                                           (float*)p_z2, BB, 256, 1024, 256, 1);
    k_final<<<(BB + 255)/256, 256>>>(c3w, c3b, out);
}

// round 5
// speedup vs baseline: 1.8874x; 1.2137x over previous
#include <cuda_runtime.h>
#include <cuda_fp16.h>
#include <cstdint>

// ---------------- problem constants ----------------
constexpr int NN   = 1048576;   // nodes
constexpr int EE   = 4194304;   // edges
constexpr int BB   = 2048;      // batch / graphs
constexpr int SEQL = 1000;      // protein sequence length
constexpr float BN_EPS = 1e-5f;

// ---------------- device scratch (static, no allocs) ----------------
__device__ __half g_h0[(size_t)NN*32];    // ping feature buffer (half)
__device__ __half g_h1[(size_t)NN*32];    // pong feature buffer (half)
__device__ double g_stats[64];            // per-channel sum / sumsq (fp32 y, double acc)
__device__ float  g_wfold[1024];          // BN-folded Wa for next layer
__device__ float  g_cfold[32];            // BN-folded constant row (sh @ Wa)
__device__ float  g_pooled[BB*32];
__device__ float  g_xj[BB*256];           // concat [xdv | xtv]
__device__ float  g_A [(size_t)BB*6656];  // histogram-weighted conv weights
__device__ float  g_T [6656*128];         // folded emb x fct_w
__device__ float  g_tb[128];              // folded bias
__device__ float  g_z1[BB*1024];
__device__ float  g_z2[BB*256];
__device__ int    g_is64;
// CSR build
__device__ int    g_deg[NN];
__device__ int    g_off[NN+1];
__device__ int    g_part[4096];
__device__ int    g_cur[NN];
__device__ int    g_csr[EE];

// ---------------- helpers ----------------
__device__ __forceinline__ long long idx_at(const void* p, long long i, int is64) {
    if (is64) return ((const long long*)p)[i];
    return (long long)((const int*)p)[i];
}

__global__ void k_detect(const int* ei) {
    int nz = 0;
    for (int i = 0; i < 256; i++) nz += (ei[2*i + 1] != 0);
    g_is64 = (nz == 0) ? 1 : 0;
}

// accumulate one half row (32 halfs = 64B) into fp32 S[32]
__device__ __forceinline__ void row_add(const __half* p, float* S) {
    const uint4* q = (const uint4*)p;
#pragma unroll
    for (int i = 0; i < 4; i++) {
        uint4 v = __ldg(&q[i]);
        const __half2* h = (const __half2*)&v;
#pragma unroll
        for (int t = 0; t < 4; t++) {
            float2 f = __half22float2(h[t]);
            S[i*8 + t*2]     += f.x;
            S[i*8 + t*2 + 1] += f.y;
        }
    }
}

// store fp32 row[32] as half (4 x uint4)
__device__ __forceinline__ void row_store_h(__half* p, const float* y) {
    uint4* q = (uint4*)p;
#pragma unroll
    for (int i = 0; i < 4; i++) {
        uint4 v;
        __half2* h = (__half2*)&v;
#pragma unroll
        for (int t = 0; t < 4; t++)
            h[t] = __floats2half2_rn(y[i*8 + t*2], y[i*8 + t*2 + 1]);
        q[i] = v;
    }
}

// ---------------- CSR build ----------------
__global__ void k_deg(const void* __restrict__ ei) {
    int e = blockIdx.x * 256 + threadIdx.x;
    long long d = idx_at(ei, (long long)EE + e, g_is64);
    atomicAdd(&g_deg[(int)d], 1);
}

__global__ void k_scan1() {
    __shared__ int s[256];
    int tid = threadIdx.x;
    int i = blockIdx.x * 256 + tid;
    int v = g_deg[i];
    s[tid] = v;
    __syncthreads();
#pragma unroll
    for (int d = 1; d < 256; d <<= 1) {
        int t = (tid >= d) ? s[tid - d] : 0;
        __syncthreads();
        s[tid] += t;
        __syncthreads();
    }
    g_off[i] = s[tid] - v;
    if (tid == 255) g_part[blockIdx.x] = s[255];
}

__global__ void k_scan2() {
    __shared__ int s[1024];
    int t = threadIdx.x;
    int base = t * 4;
    int a0 = g_part[base], a1 = g_part[base+1], a2 = g_part[base+2], a3 = g_part[base+3];
    int sum = a0 + a1 + a2 + a3;
    s[t] = sum;
    __syncthreads();
#pragma unroll
    for (int d = 1; d < 1024; d <<= 1) {
        int tv = (t >= d) ? s[t - d] : 0;
        __syncthreads();
        s[t] += tv;
        __syncthreads();
    }
    int ex = s[t] - sum;
    g_part[base]   = ex;
    g_part[base+1] = ex + a0;
    g_part[base+2] = ex + a0 + a1;
    g_part[base+3] = ex + a0 + a1 + a2;
    if (t == 1023) g_off[NN] = s[1023];
}

__global__ void k_scan3() {
    int i = blockIdx.x * 256 + threadIdx.x;
    int o = g_off[i] + g_part[blockIdx.x];
    g_off[i] = o;
    g_cur[i] = o;
}

__global__ void k_fill(const void* __restrict__ ei) {
    int e = blockIdx.x * 256 + threadIdx.x;
    int is64 = g_is64;
    int s = (int)idx_at(ei, e, is64);
    int d = (int)idx_at(ei, (long long)EE + e, is64);
    int pos = atomicAdd(&g_cur[d], 1);
    g_csr[pos] = s;
}

// ---------------- layer 0 projection: z = xd @ W1a  -> half ----------------
__global__ void k_project55(const float* __restrict__ x, const float* __restrict__ wa,
                            __half* __restrict__ zout) {
    __shared__ float ws[55*32];
    for (int i = threadIdx.x; i < 55*32; i += 128) ws[i] = wa[i];
    __syncthreads();
    int n = blockIdx.x * 128 + threadIdx.x;
    const float* xr = x + (size_t)n * 55;
    float u[32];
#pragma unroll
    for (int j = 0; j < 32; j++) u[j] = 0.f;
#pragma unroll 4
    for (int k = 0; k < 55; k++) {
        float tv = xr[k];
#pragma unroll
        for (int j4 = 0; j4 < 8; j4++) {
            float4 w4 = *(const float4*)&ws[k*32 + j4*4];
            u[j4*4+0] += tv * w4.x;
            u[j4*4+1] += tv * w4.y;
            u[j4*4+2] += tv * w4.z;
            u[j4*4+3] += tv * w4.w;
        }
    }
    row_store_h(zout + (size_t)n * 32, u);
}

// ---------------- BN fold: Wfold = diag(sc) Wa, cfold = sh @ Wa; zero stats ----------------
__global__ void k_fold(const float* __restrict__ wa, const float* __restrict__ g,
                       const float* __restrict__ b) {
    __shared__ float sc[32], sh[32];
    int t = threadIdx.x;
    if (t < 32) {
        double mu  = g_stats[t]      * (1.0 / NN);
        double var = g_stats[32 + t] * (1.0 / NN) - mu * mu;
        float s = g[t] * rsqrtf((float)var + BN_EPS);
        sc[t] = s;
        sh[t] = b[t] - (float)mu * s;
    }
    __syncthreads();
    if (t < 64) g_stats[t] = 0.0;
    int k = t >> 5;
    g_wfold[t] = sc[k] * wa[t];
    if (t < 32) {
        float a = 0.f;
        for (int k2 = 0; k2 < 32; k2++) a += sh[k2] * wa[k2*32 + t];
        g_cfold[t] = a;
    }
}

// ---------------- layer 0 gather+finish: y = relu(relu(S + b1a) @ W1b + b1b) ----------------
// S = z_n + sum_{j in N(n)} z_j  (half gathered, fp32 accum); stats on y (double)
__global__ void k_gfin0(const __half* __restrict__ zin, __half* __restrict__ yout,
                        const float* __restrict__ ba, const float* __restrict__ wb,
                        const float* __restrict__ bb) {
    __shared__ float  ws[1024];
    __shared__ float  bas[32], bbs[32];
    __shared__ float  ys[128*33];
    __shared__ double blk[64];
    int tid = threadIdx.x;
    for (int i = tid; i < 1024; i += 128) ws[i] = wb[i];
    if (tid < 32) { bas[tid] = ba[tid]; bbs[tid] = bb[tid]; }
    if (tid < 64) blk[tid] = 0.0;
    __syncthreads();
    int n = blockIdx.x * 128 + tid;
    float S[32];
#pragma unroll
    for (int j = 0; j < 32; j++) S[j] = 0.f;
    row_add(zin + (size_t)n * 32, S);          // self
    int beg = g_off[n], end = g_off[n+1];
    for (int e = beg; e < end; e++) {
        int s = __ldg(&g_csr[e]);
        row_add(zin + (size_t)s * 32, S);
    }
#pragma unroll
    for (int j = 0; j < 32; j++) S[j] = fmaxf(S[j] + bas[j], 0.f);
    float y[32];
#pragma unroll
    for (int j = 0; j < 32; j++) y[j] = 0.f;
#pragma unroll 4
    for (int k = 0; k < 32; k++) {
        float tv = S[k];
#pragma unroll
        for (int j4 = 0; j4 < 8; j4++) {
            float4 w4 = *(const float4*)&ws[k*32 + j4*4];
            y[j4*4+0] += tv * w4.x;
            y[j4*4+1] += tv * w4.y;
            y[j4*4+2] += tv * w4.z;
            y[j4*4+3] += tv * w4.w;
        }
    }
#pragma unroll
    for (int j = 0; j < 32; j++) y[j] = fmaxf(y[j] + bbs[j], 0.f);
    row_store_h(yout + (size_t)n * 32, y);
#pragma unroll
    for (int j = 0; j < 32; j++) ys[tid*33 + j] = y[j];
    __syncthreads();
    int c = tid & 31, q = tid >> 5;
    float s1 = 0.f, s2 = 0.f;
#pragma unroll 4
    for (int i = 0; i < 32; i++) {
        float v = ys[(q*32 + i)*33 + c];
        s1 += v; s2 += v * v;
    }
    atomicAdd(&blk[c],      (double)s1);
    atomicAdd(&blk[32 + c], (double)s2);
    __syncthreads();
    if (tid < 64) atomicAdd(&g_stats[tid], blk[tid]);
}

// ---------------- layers 1-4 fused: gather + BN-folded proj + MLP ----------------
// S = y_n + sum_j y_j ; u = relu(S @ Wfold + (1+deg)*cfold + ba) ; y' = relu(u @ Wb + bb)
__global__ void k_lfused(const __half* __restrict__ yin, __half* __restrict__ yout,
                         const float* __restrict__ ba, const float* __restrict__ wb,
                         const float* __restrict__ bb) {
    __shared__ float  wsA[1024];   // Wfold
    __shared__ float  wsB[1024];   // Wb
    __shared__ float  cfs[32], bas[32], bbs[32];
    __shared__ float  ys[128*33];
    __shared__ double blk[64];
    int tid = threadIdx.x;
    for (int i = tid; i < 1024; i += 128) { wsA[i] = g_wfold[i]; wsB[i] = wb[i]; }
    if (tid < 32) { cfs[tid] = g_cfold[tid]; bas[tid] = ba[tid]; bbs[tid] = bb[tid]; }
    if (tid < 64) blk[tid] = 0.0;
    __syncthreads();
    int n = blockIdx.x * 128 + tid;
    float S[32];
#pragma unroll
    for (int j = 0; j < 32; j++) S[j] = 0.f;
    row_add(yin + (size_t)n * 32, S);          // self
    int beg = g_off[n], end = g_off[n+1];
    for (int e = beg; e < end; e++) {
        int s = __ldg(&g_csr[e]);
        row_add(yin + (size_t)s * 32, S);
    }
    float cnt = (float)(1 + end - beg);
    float u[32];
#pragma unroll
    for (int j = 0; j < 32; j++) u[j] = fmaf(cnt, cfs[j], bas[j]);
#pragma unroll 4
    for (int k = 0; k < 32; k++) {
        float tv = S[k];
#pragma unroll
        for (int j4 = 0; j4 < 8; j4++) {
            float4 w4 = *(const float4*)&wsA[k*32 + j4*4];
            u[j4*4+0] += tv * w4.x;
            u[j4*4+1] += tv * w4.y;
            u[j4*4+2] += tv * w4.z;
            u[j4*4+3] += tv * w4.w;
        }
    }
#pragma unroll
    for (int j = 0; j < 32; j++) u[j] = fmaxf(u[j], 0.f);
    float y[32];
#pragma unroll
    for (int j = 0; j < 32; j++) y[j] = 0.f;
#pragma unroll 4
    for (int k = 0; k < 32; k++) {
        float tv = u[k];
#pragma unroll
        for (int j4 = 0; j4 < 8; j4++) {
            float4 w4 = *(const float4*)&wsB[k*32 + j4*4];
            y[j4*4+0] += tv * w4.x;
            y[j4*4+1] += tv * w4.y;
            y[j4*4+2] += tv * w4.z;
            y[j4*4+3] += tv * w4.w;
        }
    }
#pragma unroll
    for (int j = 0; j < 32; j++) y[j] = fmaxf(y[j] + bbs[j], 0.f);
    row_store_h(yout + (size_t)n * 32, y);
#pragma unroll
    for (int j = 0; j < 32; j++) ys[tid*33 + j] = y[j];
    __syncthreads();
    int c = tid & 31, q = tid >> 5;
    float s1 = 0.f, s2 = 0.f;
#pragma unroll 4
    for (int i = 0; i < 32; i++) {
        float v = ys[(q*32 + i)*33 + c];
        s1 += v; s2 += v * v;
    }
    atomicAdd(&blk[c],      (double)s1);
    atomicAdd(&blk[32 + c], (double)s2);
    __syncthreads();
    if (tid < 64) atomicAdd(&g_stats[tid], blk[tid]);
}

// ---------------- segment mean-pool over sorted xd_batch + final BN affine ----------------
__device__ __forceinline__ int lbound(const void* xb, int is64, long long target) {
    int lo = 0, hi = NN;
    while (lo < hi) {
        int mid = (lo + hi) >> 1;
        if (idx_at(xb, mid, is64) < target) lo = mid + 1; else hi = mid;
    }
    return lo;
}

__global__ void k_poolseg(const __half* __restrict__ ybuf, const void* __restrict__ xb,
                          const float* __restrict__ g, const float* __restrict__ b) {
    __shared__ float red[256];
    __shared__ float sc[32], sh[32];
    __shared__ int bounds[2];
    int tid = threadIdx.x;
    int bidx = blockIdx.x;
    int is64 = g_is64;
    if (tid < 2) bounds[tid] = lbound(xb, is64, (long long)(bidx + tid));
    if (tid >= 32 && tid < 64) {
        int c = tid - 32;
        double mu  = g_stats[c]      * (1.0 / NN);
        double var = g_stats[32 + c] * (1.0 / NN) - mu * mu;
        float s = g[c] * rsqrtf((float)var + BN_EPS);
        sc[c] = s;
        sh[c] = b[c] - (float)mu * s;
    }
    __syncthreads();
    int beg = bounds[0], end = bounds[1];
    int c = tid & 31, q = tid >> 5;
    float s = 0.f;
    for (int n = beg + q; n < end; n += 8)
        s += __half2float(ybuf[(size_t)n * 32 + c]);
    red[tid] = s;
    __syncthreads();
    for (int o = 128; o >= 32; o >>= 1) {
        if (tid < o) red[tid] += red[tid + o];
        __syncthreads();
    }
    if (tid < 32) {
        int cnt = end - beg;
        float m = (cnt > 0) ? (red[tid] / (float)cnt) * sc[tid] + sh[tid] : 0.f;
        g_pooled[bidx * 32 + tid] = m;
    }
}

// ---------------- protein branch: A[b,v,o,k] = sum_c [xt[b,c]==v] * w[o,c,k] ----------------
__global__ void k_abuild(const void* __restrict__ xt, const float* __restrict__ cw) {
    __shared__ float As[26*256];
    int b = blockIdx.x, tid = threadIdx.x;
    for (int i = tid; i < 26*256; i += 256) As[i] = 0.f;
    __syncthreads();
    int is64 = g_is64;
    int o = tid >> 3, k = tid & 7;
    const float* wp = cw + o * (SEQL*8) + k;
    for (int c = 0; c < SEQL; c++) {
        int v = (int)idx_at(xt, (long long)b * SEQL + c, is64);
        As[v*256 + tid] += wp[c*8];
    }
    __syncthreads();
    for (int i = tid; i < 6656; i += 256) g_A[(size_t)b * 6656 + i] = As[i];
}

// ---------------- T[(v,o,k), j] = sum_p emb[v, p+k] * fct_w[(o*121+p)*128 + j] ----------------
__global__ void k_tbuild(const float* __restrict__ emb, const float* __restrict__ fw) {
    __shared__ float es[128];
    int v = blockIdx.x >> 5, o = blockIdx.x & 31;
    int j = threadIdx.x;
    es[j] = emb[v*128 + j];
    __syncthreads();
    float acc[8];
#pragma unroll
    for (int k = 0; k < 8; k++) acc[k] = 0.f;
    for (int p = 0; p < 121; p++) {
        float w = fw[(size_t)(o*121 + p) * 128 + j];
#pragma unroll
        for (int k = 0; k < 8; k++) acc[k] += es[p + k] * w;
    }
#pragma unroll
    for (int k = 0; k < 8; k++)
        g_T[(size_t)(v*256 + o*8 + k) * 128 + j] = acc[k];
}

__global__ void k_tbias(const float* __restrict__ fw, const float* __restrict__ fb,
                        const float* __restrict__ cb) {
    int j = threadIdx.x;
    float acc = fb[j];
    for (int o = 0; o < 32; o++) {
        float cbo = cb[o];
        for (int p = 0; p < 121; p++)
            acc += cbo * fw[(size_t)(o*121 + p) * 128 + j];
    }
    g_tb[j] = acc;
}

// ---------------- generic SGEMM: C = [relu](A[MxK] @ W[KxN] + bias), row-major ----------------
__global__ void k_sgemm(const float* __restrict__ A, const float* __restrict__ W,
                        const float* __restrict__ bias, float* __restrict__ C,
                        int M, int N, int K, int ldc, int relu) {
    __shared__ float As[16][33];
    __shared__ float Ws[16][65];
    int bm = blockIdx.y * 32, bn = blockIdx.x * 64;
    int tid = threadIdx.x;
    int tm = (tid >> 4) << 2;
    int tn = (tid & 15) << 2;
    float acc[4][4];
#pragma unroll
    for (int i = 0; i < 4; i++)
#pragma unroll
        for (int j = 0; j < 4; j++) acc[i][j] = 0.f;

    for (int k0 = 0; k0 < K; k0 += 16) {
#pragma unroll
        for (int i = 0; i < 4; i++) {
            int f = tid + i * 128;
            int r = f >> 4, c = f & 15;
            As[c][r] = A[(size_t)(bm + r) * K + k0 + c];
        }
#pragma unroll
        for (int i = 0; i < 8; i++) {
            int f = tid + i * 128;
            int r = f >> 6, c = f & 63;
            Ws[r][c] = W[(size_t)(k0 + r) * N + bn + c];
        }
        __syncthreads();
#pragma unroll
        for (int k = 0; k < 16; k++) {
            float a[4], w[4];
#pragma unroll
            for (int i = 0; i < 4; i++) a[i] = As[k][tm + i];
#pragma unroll
            for (int j = 0; j < 4; j++) w[j] = Ws[k][tn + j];
#pragma unroll
            for (int i = 0; i < 4; i++)
#pragma unroll
                for (int j = 0; j < 4; j++) acc[i][j] += a[i] * w[j];
        }
        __syncthreads();
    }
#pragma unroll
    for (int i = 0; i < 4; i++)
#pragma unroll
        for (int j = 0; j < 4; j++) {
            float v = acc[i][j] + bias[bn + tn + j];
            if (relu) v = fmaxf(v, 0.f);
            C[(size_t)(bm + tm + i) * ldc + bn + tn + j] = v;
        }
}

// ---------------- final: out[b] = z2[b] . c3w + c3b ----------------
__global__ void k_final(const float* __restrict__ w, const float* __restrict__ b,
                        float* __restrict__ out) {
    int i = blockIdx.x * 256 + threadIdx.x;
    if (i >= BB) return;
    const float* zr = g_z2 + (size_t)i * 256;
    float acc = 0.f;
#pragma unroll 4
    for (int k = 0; k < 256; k++) acc += zr[k] * w[k];
    out[i] = acc + b[0];
}

// ---------------- host launcher ----------------
extern "C" void kernel_launch(void* const* d_in, const int* in_sizes, int n_in,
                              void* d_out, int out_size) {
    (void)in_sizes; (void)n_in; (void)out_size;
    const float* xd     = (const float*)d_in[0];
    const void*  ei     = d_in[1];
    const void*  xb     = d_in[2];
    const void*  xt     = d_in[3];
    const float* w1a    = (const float*)d_in[4];
    const float* b1a    = (const float*)d_in[5];
    const float* w1b    = (const float*)d_in[6];
    const float* b1b    = (const float*)d_in[7];
    const float* wa     = (const float*)d_in[8];
    const float* ba     = (const float*)d_in[9];
    const float* wb     = (const float*)d_in[10];
    const float* bb     = (const float*)d_in[11];
    const float* bng    = (const float*)d_in[12];
    const float* bnb    = (const float*)d_in[13];
    const float* fcd_w  = (const float*)d_in[14];
    const float* fcd_b  = (const float*)d_in[15];
    const float* emb    = (const float*)d_in[16];
    const float* conv_w = (const float*)d_in[17];
    const float* conv_b = (const float*)d_in[18];
    const float* fct_w  = (const float*)d_in[19];
    const float* fct_b  = (const float*)d_in[20];
    const float* c1w    = (const float*)d_in[21];
    const float* c1b    = (const float*)d_in[22];
    const float* c2w    = (const float*)d_in[23];
    const float* c2b    = (const float*)d_in[24];
    const float* c3w    = (const float*)d_in[25];
    const float* c3b    = (const float*)d_in[26];
    float* out = (float*)d_out;

    void *p_stats, *p_pooled, *p_xj, *p_A, *p_T, *p_tb, *p_z1, *p_deg, *p_h0, *p_h1;
    cudaGetSymbolAddress(&p_stats,  g_stats);
    cudaGetSymbolAddress(&p_pooled, g_pooled);
    cudaGetSymbolAddress(&p_xj,     g_xj);
    cudaGetSymbolAddress(&p_A,      g_A);
    cudaGetSymbolAddress(&p_T,      g_T);
    cudaGetSymbolAddress(&p_tb,     g_tb);
    cudaGetSymbolAddress(&p_z1,     g_z1);
    cudaGetSymbolAddress(&p_deg,    g_deg);
    cudaGetSymbolAddress(&p_h0,     g_h0);
    cudaGetSymbolAddress(&p_h1,     g_h1);
    void* p_z2; cudaGetSymbolAddress(&p_z2, g_z2);

    __half* hb[2] = { (__half*)p_h0, (__half*)p_h1 };

    k_detect<<<1, 1>>>((const int*)ei);
    cudaMemsetAsync(p_stats, 0, 64 * sizeof(double));

    // ----- CSR build (once, amortized over 5 layers) -----
    cudaMemsetAsync(p_deg, 0, NN * sizeof(int));
    k_deg  <<<EE/256, 256>>>(ei);
    k_scan1<<<4096, 256>>>();
    k_scan2<<<1, 1024>>>();
    k_scan3<<<4096, 256>>>();
    k_fill <<<EE/256, 256>>>(ei);

    // ----- layer 0: project 55->32, then gather+MLP -----
    k_project55<<<NN/128, 128>>>(xd, w1a, hb[0]);
    k_gfin0<<<NN/128, 128>>>(hb[0], hb[1], b1a, w1b, b1b);

    // ----- layers 1-4: fused gather + BN-folded projection + MLP (ping-pong) -----
    for (int L = 1; L < 5; L++) {
        k_fold<<<1, 1024>>>(wa + (L - 1) * 1024, bng + (L - 1) * 32, bnb + (L - 1) * 32);
        const __half* yin = hb[L & 1];
        __half* yout      = hb[(L + 1) & 1];
        k_lfused<<<NN/128, 128>>>(yin, yout,
                                  ba + (L - 1) * 32, wb + (L - 1) * 1024, bb + (L - 1) * 32);
    }

    // ----- segment mean pool (+ final BN affine) + fc1_xd -----
    // after L4 the output lives in hb[(4+1)&1] = hb[1]
    k_poolseg<<<BB, 256>>>(hb[1], xb, bng + 4 * 32, bnb + 4 * 32);
    k_sgemm<<<dim3(128/64, BB/32), 128>>>((const float*)p_pooled, fcd_w, fcd_b,
                                          (float*)p_xj, BB, 128, 32, 256, 1);

    // ----- protein branch: histogram + folded conv/fc GEMM -----
    k_abuild<<<BB, 256>>>(xt, conv_w);
    k_tbuild<<<26*32, 128>>>(emb, fct_w);
    k_tbias<<<1, 128>>>(fct_w, fct_b, conv_b);
    k_sgemm<<<dim3(128/64, BB/32), 128>>>((const float*)p_A, (const float*)p_T,
                                          (const float*)p_tb, (float*)p_xj + 128,
                                          BB, 128, 6656, 256, 0);

    // ----- classifier -----
    k_sgemm<<<dim3(1024/64, BB/32), 128>>>((const float*)p_xj, c1w, c1b,
                                           (float*)p_z1, BB, 1024, 256, 1024, 1);
    k_sgemm<<<dim3(256/64,  BB/32), 128>>>((const float*)p_z1, c2w, c2b,
                                           (float*)p_z2, BB, 256, 1024, 256, 1);
    k_final<<<(BB + 255)/256, 256>>>(c3w, c3b, out);
}